// round 14
// baseline (speedup 1.0000x reference)
#include <cuda_runtime.h>

// ---------------- problem constants ----------------
#define H      384          // hidden
#define BF     150          // bond feature dim
#define AF     139          // atom feature dim
#define NAT    32769        // 1 + M*A atoms
#define NBD    131073       // 1 + M*4*A directed bonds
#define MMOL   1024         // molecules
#define KCAT   (AF + H)     // 523, concat GEMM K

// ---------------- device scratch (no cudaMalloc allowed) ----------------
__device__ float g_inp  [(size_t)NBD * H];
__device__ float g_msgA [(size_t)NBD * H];
__device__ float g_msgB [(size_t)NBD * H];
__device__ float g_amsg [(size_t)NAT * H];
__device__ float g_atomh[(size_t)NAT * H];

// ==========================================================================
// Tiled SGEMM, 128x128 tile, BK=16, 256 threads, 8x8 per-thread microtile.
// MODE 0: C = f_bonds @ W_i          -> out0 = raw (inp), out1 = relu
// MODE 1: C = (amsg[b2a]-msg[b2revb]) @ W_h  -> out1 = relu(inp + C)
// MODE 2: C = concat(f_atoms, amsg) @ W_o    -> out1 = relu(C + bias)
// B (weights) are always row-major [K x 384].
// ==========================================================================
template<int MODE>
__global__ __launch_bounds__(256)
void sgemm_k(int Mrows, int K,
             const float* __restrict__ A,
             const float* __restrict__ B,
             const float* __restrict__ Cbase,
             const float* __restrict__ bias,
             float* __restrict__ out0,
             float* __restrict__ out1,
             const float* __restrict__ amsg,
             const float* __restrict__ msg_in,
             const int*   __restrict__ b2a,
             const int*   __restrict__ b2revb,
             const float* __restrict__ f_atoms)
{
    __shared__ float sA[16][128];
    __shared__ float sB[16][128];
    __shared__ int   sIa[128];
    __shared__ int   sIb[128];

    const int tid  = threadIdx.x;
    const int row0 = blockIdx.x * 128;
    const int col0 = blockIdx.y * 128;
    const int ty   = tid >> 4;   // 0..15  -> rows ty*8..ty*8+7
    const int tx   = tid & 15;   // 0..15  -> cols tx*8..tx*8+7

    if (MODE == 1) {
        if (tid < 128) {
            int r = row0 + tid;
            sIa[tid] = (r < Mrows) ? b2a[r]    : 0;
            sIb[tid] = (r < Mrows) ? b2revb[r] : 0;
        }
        __syncthreads();
    }

    float acc[8][8];
    #pragma unroll
    for (int i = 0; i < 8; i++)
        #pragma unroll
        for (int j = 0; j < 8; j++) acc[i][j] = 0.f;

    for (int k0 = 0; k0 < K; k0 += 16) {
        // ---- load A tile (with fused gather / concat) into sA[k][row] ----
        #pragma unroll
        for (int i = 0; i < 8; i++) {
            int idx  = tid + i * 256;
            int r    = idx >> 4;
            int kk   = idx & 15;
            int grow = row0 + r;
            int gk   = k0 + kk;
            float v  = 0.f;
            if (grow < Mrows && gk < K) {
                if (MODE == 0)
                    v = A[(size_t)grow * BF + gk];
                else if (MODE == 1)
                    v = amsg[(size_t)sIa[r] * H + gk] - msg_in[(size_t)sIb[r] * H + gk];
                else
                    v = (gk < AF) ? f_atoms[(size_t)grow * AF + gk]
                                  : amsg[(size_t)grow * H + (gk - AF)];
            }
            sA[kk][r] = v;
        }
        // ---- load B tile ----
        #pragma unroll
        for (int i = 0; i < 8; i++) {
            int idx = tid + i * 256;
            int kk  = idx >> 7;
            int n   = idx & 127;
            int gk  = k0 + kk;
            sB[kk][n] = (gk < K) ? B[(size_t)gk * H + col0 + n] : 0.f;
        }
        __syncthreads();

        #pragma unroll
        for (int kk = 0; kk < 16; kk++) {
            float4 a0 = *(const float4*)&sA[kk][ty * 8];
            float4 a1 = *(const float4*)&sA[kk][ty * 8 + 4];
            float4 b0 = *(const float4*)&sB[kk][tx * 8];
            float4 b1 = *(const float4*)&sB[kk][tx * 8 + 4];
            float av[8] = {a0.x, a0.y, a0.z, a0.w, a1.x, a1.y, a1.z, a1.w};
            float bv[8] = {b0.x, b0.y, b0.z, b0.w, b1.x, b1.y, b1.z, b1.w};
            #pragma unroll
            for (int i = 0; i < 8; i++)
                #pragma unroll
                for (int j = 0; j < 8; j++)
                    acc[i][j] += av[i] * bv[j];
        }
        __syncthreads();
    }

    // ---- epilogue (float4 stores) ----
    #pragma unroll
    for (int i = 0; i < 8; i++) {
        int grow = row0 + ty * 8 + i;
        if (grow >= Mrows) continue;
        size_t base = (size_t)grow * H + col0 + tx * 8;
        #pragma unroll
        for (int jj = 0; jj < 2; jj++) {
            float4 v;
            v.x = acc[i][jj * 4 + 0]; v.y = acc[i][jj * 4 + 1];
            v.z = acc[i][jj * 4 + 2]; v.w = acc[i][jj * 4 + 3];
            if (MODE == 0) {
                *(float4*)(out0 + base + jj * 4) = v;
                float4 r = {fmaxf(v.x, 0.f), fmaxf(v.y, 0.f), fmaxf(v.z, 0.f), fmaxf(v.w, 0.f)};
                *(float4*)(out1 + base + jj * 4) = r;
            } else if (MODE == 1) {
                float4 c = *(const float4*)(Cbase + base + jj * 4);
                float4 r = {fmaxf(v.x + c.x, 0.f), fmaxf(v.y + c.y, 0.f),
                            fmaxf(v.z + c.z, 0.f), fmaxf(v.w + c.w, 0.f)};
                *(float4*)(out1 + base + jj * 4) = r;
            } else {
                int n = col0 + tx * 8 + jj * 4;
                float4 bb = *(const float4*)(bias + n);
                float4 r = {fmaxf(v.x + bb.x, 0.f), fmaxf(v.y + bb.y, 0.f),
                            fmaxf(v.z + bb.z, 0.f), fmaxf(v.w + bb.w, 0.f)};
                *(float4*)(out1 + base + jj * 4) = r;
            }
        }
    }
}

// ==========================================================================
// a_msg[a] = sum_{j<4} message[a2b[a][j]]   (float4 vectorized gather)
// ==========================================================================
__global__ __launch_bounds__(256)
void gather_amsg_k(const float* __restrict__ msg,
                   const int*   __restrict__ a2b,
                   float*       __restrict__ amsg)
{
    int t = blockIdx.x * blockDim.x + threadIdx.x;
    const int total = NAT * (H / 4);
    if (t >= total) return;
    int a = t / (H / 4);
    int c = t % (H / 4);
    int4 nb = *(const int4*)&a2b[(size_t)a * 4];
    const float4* m = (const float4*)msg;
    float4 v0 = m[(size_t)nb.x * (H / 4) + c];
    float4 v1 = m[(size_t)nb.y * (H / 4) + c];
    float4 v2 = m[(size_t)nb.z * (H / 4) + c];
    float4 v3 = m[(size_t)nb.w * (H / 4) + c];
    float4 r;
    r.x = v0.x + v1.x + v2.x + v3.x;
    r.y = v0.y + v1.y + v2.y + v3.y;
    r.z = v0.z + v1.z + v2.z + v3.z;
    r.w = v0.w + v1.w + v2.w + v3.w;
    ((float4*)amsg)[t] = r;
}

// ==========================================================================
// Attention readout: one block per molecule (32 atoms x 384 hidden).
//   q = cur @ W_a ; S = softmax(q @ cur^T) ; z = S @ cur ;
//   att_h = relu(z @ W_b + b_b) ; out[m] = sum_a (cur + att_h)
// smem: cur(48K) + q/z(48K) + W tile(48K) + S(4K) + red(6K) = ~158 KB dynamic
// ==========================================================================
#define ATT_SMEM ((3 * 32 * H + 32 * 32 + 4 * H) * sizeof(float))

__global__ __launch_bounds__(256)
void attention_k(const float* __restrict__ atomh,
                 const float* __restrict__ W_a,
                 const float* __restrict__ W_b,
                 const float* __restrict__ b_b,
                 float*       __restrict__ out)
{
    extern __shared__ float sm[];
    float* s_cur = sm;                 // 32*H
    float* s_q   = s_cur + 32 * H;     // 32*H  (reused for z)
    float* s_W   = s_q   + 32 * H;     // 32*H  (K-tile of W)
    float* s_S   = s_W   + 32 * H;     // 32*32
    float* s_red = s_S   + 32 * 32;    // 4*H

    const int m   = blockIdx.x;
    const int tid = threadIdx.x;
    const int tx  = tid & 63;          // h columns {tx, tx+64, ... tx+320}
    const int ty  = tid >> 6;          // rows ty*8..ty*8+7

    // load cur (atoms 1 + m*32 .. 1 + m*32 + 31)
    {
        const float4* src = (const float4*)(atomh + (size_t)(1 + m * 32) * H);
        float4* dst = (float4*)s_cur;
        #pragma unroll
        for (int i = 0; i < 12; i++) dst[tid + i * 256] = src[tid + i * 256];
    }
    __syncthreads();

    // ---- q = cur @ W_a ----
    float acc[8][6];
    for (int i = 0; i < 8; i++)
        for (int j = 0; j < 6; j++) acc[i][j] = 0.f;
    for (int k0 = 0; k0 < H; k0 += 32) {
        const float4* wsrc = (const float4*)(W_a + (size_t)k0 * H);
        float4* wdst = (float4*)s_W;
        #pragma unroll
        for (int i = 0; i < 12; i++) wdst[tid + i * 256] = wsrc[tid + i * 256];
        __syncthreads();
        #pragma unroll 4
        for (int kk = 0; kk < 32; kk++) {
            float av[8], bv[6];
            #pragma unroll
            for (int i = 0; i < 8; i++) av[i] = s_cur[(ty * 8 + i) * H + k0 + kk];
            #pragma unroll
            for (int j = 0; j < 6; j++) bv[j] = s_W[kk * H + tx + j * 64];
            #pragma unroll
            for (int i = 0; i < 8; i++)
                #pragma unroll
                for (int j = 0; j < 6; j++) acc[i][j] += av[i] * bv[j];
        }
        __syncthreads();
    }
    #pragma unroll
    for (int i = 0; i < 8; i++)
        #pragma unroll
        for (int j = 0; j < 6; j++)
            s_q[(ty * 8 + i) * H + tx + j * 64] = acc[i][j];
    __syncthreads();

    // ---- scores S[a][b] = <q[a], cur[b]> ----
    {
        int a  = tid >> 3;
        int b0 = (tid & 7) * 4;
        float s0 = 0, s1 = 0, s2 = 0, s3 = 0;
        for (int h = 0; h < H; h++) {
            float qa = s_q[a * H + h];
            s0 += qa * s_cur[(b0 + 0) * H + h];
            s1 += qa * s_cur[(b0 + 1) * H + h];
            s2 += qa * s_cur[(b0 + 2) * H + h];
            s3 += qa * s_cur[(b0 + 3) * H + h];
        }
        s_S[a * 32 + b0 + 0] = s0;
        s_S[a * 32 + b0 + 1] = s1;
        s_S[a * 32 + b0 + 2] = s2;
        s_S[a * 32 + b0 + 3] = s3;
    }
    __syncthreads();

    // ---- softmax rows (8 warps x 4 rows, lane = b) ----
    {
        int warp = tid >> 5, lane = tid & 31;
        for (int a = warp; a < 32; a += 8) {
            float v  = s_S[a * 32 + lane];
            float mx = v;
            #pragma unroll
            for (int o = 16; o; o >>= 1) mx = fmaxf(mx, __shfl_xor_sync(0xffffffffu, mx, o));
            float e = __expf(v - mx);
            float s = e;
            #pragma unroll
            for (int o = 16; o; o >>= 1) s += __shfl_xor_sync(0xffffffffu, s, o);
            s_S[a * 32 + lane] = e / s;
        }
    }
    __syncthreads();

    // ---- z = S @ cur ----
    float z[8][6];
    for (int i = 0; i < 8; i++)
        for (int j = 0; j < 6; j++) z[i][j] = 0.f;
    for (int b = 0; b < 32; b++) {
        float p[8], c[6];
        #pragma unroll
        for (int i = 0; i < 8; i++) p[i] = s_S[(ty * 8 + i) * 32 + b];
        #pragma unroll
        for (int j = 0; j < 6; j++) c[j] = s_cur[b * H + tx + j * 64];
        #pragma unroll
        for (int i = 0; i < 8; i++)
            #pragma unroll
            for (int j = 0; j < 6; j++) z[i][j] += p[i] * c[j];
    }
    __syncthreads();             // everyone is done reading s_q
    #pragma unroll
    for (int i = 0; i < 8; i++)
        #pragma unroll
        for (int j = 0; j < 6; j++)
            s_q[(ty * 8 + i) * H + tx + j * 64] = z[i][j];   // z now lives in s_q
    __syncthreads();

    // ---- att_h = relu(z @ W_b + b_b), accumulate columns ----
    for (int i = 0; i < 8; i++)
        for (int j = 0; j < 6; j++) acc[i][j] = 0.f;
    for (int k0 = 0; k0 < H; k0 += 32) {
        const float4* wsrc = (const float4*)(W_b + (size_t)k0 * H);
        float4* wdst = (float4*)s_W;
        #pragma unroll
        for (int i = 0; i < 12; i++) wdst[tid + i * 256] = wsrc[tid + i * 256];
        __syncthreads();
        #pragma unroll 4
        for (int kk = 0; kk < 32; kk++) {
            float av[8], bv[6];
            #pragma unroll
            for (int i = 0; i < 8; i++) av[i] = s_q[(ty * 8 + i) * H + k0 + kk];
            #pragma unroll
            for (int j = 0; j < 6; j++) bv[j] = s_W[kk * H + tx + j * 64];
            #pragma unroll
            for (int i = 0; i < 8; i++)
                #pragma unroll
                for (int j = 0; j < 6; j++) acc[i][j] += av[i] * bv[j];
        }
        __syncthreads();
    }
    #pragma unroll
    for (int j = 0; j < 6; j++) {
        int h = tx + j * 64;
        float bb = b_b[h];
        float ps = 0.f;
        #pragma unroll
        for (int i = 0; i < 8; i++) ps += fmaxf(acc[i][j] + bb, 0.f);
        s_red[ty * H + h] = ps;
    }
    __syncthreads();
    if (ty == 0) {
        #pragma unroll
        for (int j = 0; j < 6; j++) {
            int h = tx + j * 64;
            float total = s_red[h] + s_red[H + h] + s_red[2 * H + h] + s_red[3 * H + h];
            float cs = 0.f;
            for (int a = 0; a < 32; a++) cs += s_cur[a * H + h];
            out[(size_t)m * H + h] = total + cs;
        }
    }
}

// ==========================================================================
extern "C" void kernel_launch(void* const* d_in, const int* in_sizes, int n_in,
                              void* d_out, int out_size)
{
    const float* f_atoms = (const float*)d_in[0];
    const float* f_bonds = (const float*)d_in[1];
    const float* W_i     = (const float*)d_in[2];
    const float* W_h     = (const float*)d_in[3];
    const float* W_o     = (const float*)d_in[4];
    const float* b_o     = (const float*)d_in[5];
    const float* W_a     = (const float*)d_in[6];
    const float* W_b     = (const float*)d_in[7];
    const float* b_b     = (const float*)d_in[8];
    const int*   a2b     = (const int*)d_in[9];
    const int*   b2a     = (const int*)d_in[10];
    const int*   b2revb  = (const int*)d_in[11];
    float*       out     = (float*)d_out;

    float *inp, *msgA, *msgB, *amsg, *atomh;
    cudaGetSymbolAddress((void**)&inp,   g_inp);
    cudaGetSymbolAddress((void**)&msgA,  g_msgA);
    cudaGetSymbolAddress((void**)&msgB,  g_msgB);
    cudaGetSymbolAddress((void**)&amsg,  g_amsg);
    cudaGetSymbolAddress((void**)&atomh, g_atomh);

    const dim3 blk(256);
    const dim3 gBond((NBD + 127) / 128, 3);
    const dim3 gAtom((NAT + 127) / 128, 3);
    const int  gGather = (NAT * (H / 4) + 255) / 256;

    // message^0 = relu(inp), inp = f_bonds @ W_i
    sgemm_k<0><<<gBond, blk>>>(NBD, BF, f_bonds, W_i, nullptr, nullptr,
                               inp, msgA, nullptr, nullptr, nullptr, nullptr, nullptr);

    // 3 message-passing steps (ping-pong A/B)
    float* cur = msgA;
    float* nxt = msgB;
    for (int d = 0; d < 3; d++) {
        gather_amsg_k<<<gGather, 256>>>(cur, a2b, amsg);
        sgemm_k<1><<<gBond, blk>>>(NBD, H, nullptr, W_h + (size_t)d * H * H, inp, nullptr,
                                   nullptr, nxt, amsg, cur, b2a, b2revb, nullptr);
        float* t = cur; cur = nxt; nxt = t;
    }

    // final a_msg + atom readout: atom_h = relu(concat(f_atoms, a_msg) @ W_o + b_o)
    gather_amsg_k<<<gGather, 256>>>(cur, a2b, amsg);
    sgemm_k<2><<<gAtom, blk>>>(NAT, KCAT, nullptr, W_o, nullptr, b_o,
                               nullptr, atomh, amsg, nullptr, nullptr, nullptr, f_atoms);

    // per-molecule attention + reduce
    cudaFuncSetAttribute(attention_k, cudaFuncAttributeMaxDynamicSharedMemorySize,
                         (int)ATT_SMEM);
    attention_k<<<MMOL, 256, ATT_SMEM>>>(atomh, W_a, W_b, b_b, out);
}

// round 15
// speedup vs baseline: 1.0010x; 1.0010x over previous
#include <cuda_runtime.h>

// ---------------- problem constants ----------------
#define H      384          // hidden
#define BF     150          // bond feature dim
#define AF     139          // atom feature dim
#define NAT    32769        // 1 + M*A atoms
#define NBD    131073       // 1 + M*4*A directed bonds
#define MMOL   1024         // molecules
#define KCAT   (AF + H)     // 523, concat GEMM K

// ---------------- device scratch (no cudaMalloc allowed) ----------------
__device__ float g_inp  [(size_t)NBD * H];
__device__ float g_msgA [(size_t)NBD * H];
__device__ float g_msgB [(size_t)NBD * H];
__device__ float g_amsg [(size_t)NAT * H];
__device__ float g_atomh[(size_t)NAT * H];

// ==========================================================================
// Tiled SGEMM, 128x128 tile, BK=16, 256 threads, 8x8 per-thread microtile.
// MODE 0: C = f_bonds @ W_i          -> out0 = raw (inp), out1 = relu
// MODE 1: C = (amsg[b2a]-msg[b2revb]) @ W_h  -> out1 = relu(inp + C)
// MODE 2: C = concat(f_atoms, amsg) @ W_o    -> out1 = relu(C + bias)
// B (weights) are always row-major [K x 384].
// ==========================================================================
template<int MODE>
__global__ __launch_bounds__(256)
void sgemm_k(int Mrows, int K,
             const float* __restrict__ A,
             const float* __restrict__ B,
             const float* __restrict__ Cbase,
             const float* __restrict__ bias,
             float* __restrict__ out0,
             float* __restrict__ out1,
             const float* __restrict__ amsg,
             const float* __restrict__ msg_in,
             const int*   __restrict__ b2a,
             const int*   __restrict__ b2revb,
             const float* __restrict__ f_atoms)
{
    __shared__ float sA[16][128];
    __shared__ float sB[16][128];
    __shared__ int   sIa[128];
    __shared__ int   sIb[128];

    const int tid  = threadIdx.x;
    const int row0 = blockIdx.x * 128;
    const int col0 = blockIdx.y * 128;
    const int ty   = tid >> 4;   // 0..15  -> rows ty*8..ty*8+7
    const int tx   = tid & 15;   // 0..15  -> cols tx*8..tx*8+7

    if (MODE == 1) {
        if (tid < 128) {
            int r = row0 + tid;
            sIa[tid] = (r < Mrows) ? b2a[r]    : 0;
            sIb[tid] = (r < Mrows) ? b2revb[r] : 0;
        }
        __syncthreads();
    }

    float acc[8][8];
    #pragma unroll
    for (int i = 0; i < 8; i++)
        #pragma unroll
        for (int j = 0; j < 8; j++) acc[i][j] = 0.f;

    for (int k0 = 0; k0 < K; k0 += 16) {
        // ---- load A tile (with fused gather / concat) into sA[k][row] ----
        #pragma unroll
        for (int i = 0; i < 8; i++) {
            int idx  = tid + i * 256;
            int r    = idx >> 4;
            int kk   = idx & 15;
            int grow = row0 + r;
            int gk   = k0 + kk;
            float v  = 0.f;
            if (grow < Mrows && gk < K) {
                if (MODE == 0)
                    v = A[(size_t)grow * BF + gk];
                else if (MODE == 1)
                    v = amsg[(size_t)sIa[r] * H + gk] - msg_in[(size_t)sIb[r] * H + gk];
                else
                    v = (gk < AF) ? f_atoms[(size_t)grow * AF + gk]
                                  : amsg[(size_t)grow * H + (gk - AF)];
            }
            sA[kk][r] = v;
        }
        // ---- load B tile ----
        #pragma unroll
        for (int i = 0; i < 8; i++) {
            int idx = tid + i * 256;
            int kk  = idx >> 7;
            int n   = idx & 127;
            int gk  = k0 + kk;
            sB[kk][n] = (gk < K) ? B[(size_t)gk * H + col0 + n] : 0.f;
        }
        __syncthreads();

        #pragma unroll
        for (int kk = 0; kk < 16; kk++) {
            float4 a0 = *(const float4*)&sA[kk][ty * 8];
            float4 a1 = *(const float4*)&sA[kk][ty * 8 + 4];
            float4 b0 = *(const float4*)&sB[kk][tx * 8];
            float4 b1 = *(const float4*)&sB[kk][tx * 8 + 4];
            float av[8] = {a0.x, a0.y, a0.z, a0.w, a1.x, a1.y, a1.z, a1.w};
            float bv[8] = {b0.x, b0.y, b0.z, b0.w, b1.x, b1.y, b1.z, b1.w};
            #pragma unroll
            for (int i = 0; i < 8; i++)
                #pragma unroll
                for (int j = 0; j < 8; j++)
                    acc[i][j] += av[i] * bv[j];
        }
        __syncthreads();
    }

    // ---- epilogue (float4 stores) ----
    #pragma unroll
    for (int i = 0; i < 8; i++) {
        int grow = row0 + ty * 8 + i;
        if (grow >= Mrows) continue;
        size_t base = (size_t)grow * H + col0 + tx * 8;
        #pragma unroll
        for (int jj = 0; jj < 2; jj++) {
            float4 v;
            v.x = acc[i][jj * 4 + 0]; v.y = acc[i][jj * 4 + 1];
            v.z = acc[i][jj * 4 + 2]; v.w = acc[i][jj * 4 + 3];
            if (MODE == 0) {
                *(float4*)(out0 + base + jj * 4) = v;
                float4 r = {fmaxf(v.x, 0.f), fmaxf(v.y, 0.f), fmaxf(v.z, 0.f), fmaxf(v.w, 0.f)};
                *(float4*)(out1 + base + jj * 4) = r;
            } else if (MODE == 1) {
                float4 c = *(const float4*)(Cbase + base + jj * 4);
                float4 r = {fmaxf(v.x + c.x, 0.f), fmaxf(v.y + c.y, 0.f),
                            fmaxf(v.z + c.z, 0.f), fmaxf(v.w + c.w, 0.f)};
                *(float4*)(out1 + base + jj * 4) = r;
            } else {
                int n = col0 + tx * 8 + jj * 4;
                float4 bb = *(const float4*)(bias + n);
                float4 r = {fmaxf(v.x + bb.x, 0.f), fmaxf(v.y + bb.y, 0.f),
                            fmaxf(v.z + bb.z, 0.f), fmaxf(v.w + bb.w, 0.f)};
                *(float4*)(out1 + base + jj * 4) = r;
            }
        }
    }
}

// ==========================================================================
// a_msg[a] = sum_{j<4} message[a2b[a][j]]   (float4 vectorized gather)
// ==========================================================================
__global__ __launch_bounds__(256)
void gather_amsg_k(const float* __restrict__ msg,
                   const int*   __restrict__ a2b,
                   float*       __restrict__ amsg)
{
    int t = blockIdx.x * blockDim.x + threadIdx.x;
    const int total = NAT * (H / 4);
    if (t >= total) return;
    int a = t / (H / 4);
    int c = t % (H / 4);
    int4 nb = *(const int4*)&a2b[(size_t)a * 4];
    const float4* m = (const float4*)msg;
    float4 v0 = m[(size_t)nb.x * (H / 4) + c];
    float4 v1 = m[(size_t)nb.y * (H / 4) + c];
    float4 v2 = m[(size_t)nb.z * (H / 4) + c];
    float4 v3 = m[(size_t)nb.w * (H / 4) + c];
    float4 r;
    r.x = v0.x + v1.x + v2.x + v3.x;
    r.y = v0.y + v1.y + v2.y + v3.y;
    r.z = v0.z + v1.z + v2.z + v3.z;
    r.w = v0.w + v1.w + v2.w + v3.w;
    ((float4*)amsg)[t] = r;
}

// ==========================================================================
// Attention readout: one block per molecule (32 atoms x 384 hidden).
//   q = cur @ W_a ; S = softmax(q @ cur^T) ; z = S @ cur ;
//   att_h = relu(z @ W_b + b_b) ; out[m] = sum_a (cur + att_h)
// smem: cur(48K) + q/z(48K) + W tile(48K) + S(4K) + red(6K) = ~158 KB dynamic
// ==========================================================================
#define ATT_SMEM ((3 * 32 * H + 32 * 32 + 4 * H) * sizeof(float))

__global__ __launch_bounds__(256)
void attention_k(const float* __restrict__ atomh,
                 const float* __restrict__ W_a,
                 const float* __restrict__ W_b,
                 const float* __restrict__ b_b,
                 float*       __restrict__ out)
{
    extern __shared__ float sm[];
    float* s_cur = sm;                 // 32*H
    float* s_q   = s_cur + 32 * H;     // 32*H  (reused for z)
    float* s_W   = s_q   + 32 * H;     // 32*H  (K-tile of W)
    float* s_S   = s_W   + 32 * H;     // 32*32
    float* s_red = s_S   + 32 * 32;    // 4*H

    const int m   = blockIdx.x;
    const int tid = threadIdx.x;
    const int tx  = tid & 63;          // h columns {tx, tx+64, ... tx+320}
    const int ty  = tid >> 6;          // rows ty*8..ty*8+7

    // load cur (atoms 1 + m*32 .. 1 + m*32 + 31)
    {
        const float4* src = (const float4*)(atomh + (size_t)(1 + m * 32) * H);
        float4* dst = (float4*)s_cur;
        #pragma unroll
        for (int i = 0; i < 12; i++) dst[tid + i * 256] = src[tid + i * 256];
    }
    __syncthreads();

    // ---- q = cur @ W_a ----
    float acc[8][6];
    for (int i = 0; i < 8; i++)
        for (int j = 0; j < 6; j++) acc[i][j] = 0.f;
    for (int k0 = 0; k0 < H; k0 += 32) {
        const float4* wsrc = (const float4*)(W_a + (size_t)k0 * H);
        float4* wdst = (float4*)s_W;
        #pragma unroll
        for (int i = 0; i < 12; i++) wdst[tid + i * 256] = wsrc[tid + i * 256];
        __syncthreads();
        #pragma unroll 4
        for (int kk = 0; kk < 32; kk++) {
            float av[8], bv[6];
            #pragma unroll
            for (int i = 0; i < 8; i++) av[i] = s_cur[(ty * 8 + i) * H + k0 + kk];
            #pragma unroll
            for (int j = 0; j < 6; j++) bv[j] = s_W[kk * H + tx + j * 64];
            #pragma unroll
            for (int i = 0; i < 8; i++)
                #pragma unroll
                for (int j = 0; j < 6; j++) acc[i][j] += av[i] * bv[j];
        }
        __syncthreads();
    }
    #pragma unroll
    for (int i = 0; i < 8; i++)
        #pragma unroll
        for (int j = 0; j < 6; j++)
            s_q[(ty * 8 + i) * H + tx + j * 64] = acc[i][j];
    __syncthreads();

    // ---- scores S[a][b] = <q[a], cur[b]> ----
    {
        int a  = tid >> 3;
        int b0 = (tid & 7) * 4;
        float s0 = 0, s1 = 0, s2 = 0, s3 = 0;
        for (int h = 0; h < H; h++) {
            float qa = s_q[a * H + h];
            s0 += qa * s_cur[(b0 + 0) * H + h];
            s1 += qa * s_cur[(b0 + 1) * H + h];
            s2 += qa * s_cur[(b0 + 2) * H + h];
            s3 += qa * s_cur[(b0 + 3) * H + h];
        }
        s_S[a * 32 + b0 + 0] = s0;
        s_S[a * 32 + b0 + 1] = s1;
        s_S[a * 32 + b0 + 2] = s2;
        s_S[a * 32 + b0 + 3] = s3;
    }
    __syncthreads();

    // ---- softmax rows (8 warps x 4 rows, lane = b) ----
    {
        int warp = tid >> 5, lane = tid & 31;
        for (int a = warp; a < 32; a += 8) {
            float v  = s_S[a * 32 + lane];
            float mx = v;
            #pragma unroll
            for (int o = 16; o; o >>= 1) mx = fmaxf(mx, __shfl_xor_sync(0xffffffffu, mx, o));
            float e = __expf(v - mx);
            float s = e;
            #pragma unroll
            for (int o = 16; o; o >>= 1) s += __shfl_xor_sync(0xffffffffu, s, o);
            s_S[a * 32 + lane] = e / s;
        }
    }
    __syncthreads();

    // ---- z = S @ cur ----
    float z[8][6];
    for (int i = 0; i < 8; i++)
        for (int j = 0; j < 6; j++) z[i][j] = 0.f;
    for (int b = 0; b < 32; b++) {
        float p[8], c[6];
        #pragma unroll
        for (int i = 0; i < 8; i++) p[i] = s_S[(ty * 8 + i) * 32 + b];
        #pragma unroll
        for (int j = 0; j < 6; j++) c[j] = s_cur[b * H + tx + j * 64];
        #pragma unroll
        for (int i = 0; i < 8; i++)
            #pragma unroll
            for (int j = 0; j < 6; j++) z[i][j] += p[i] * c[j];
    }
    __syncthreads();             // everyone is done reading s_q
    #pragma unroll
    for (int i = 0; i < 8; i++)
        #pragma unroll
        for (int j = 0; j < 6; j++)
            s_q[(ty * 8 + i) * H + tx + j * 64] = z[i][j];   // z now lives in s_q
    __syncthreads();

    // ---- att_h = relu(z @ W_b + b_b), accumulate columns ----
    for (int i = 0; i < 8; i++)
        for (int j = 0; j < 6; j++) acc[i][j] = 0.f;
    for (int k0 = 0; k0 < H; k0 += 32) {
        const float4* wsrc = (const float4*)(W_b + (size_t)k0 * H);
        float4* wdst = (float4*)s_W;
        #pragma unroll
        for (int i = 0; i < 12; i++) wdst[tid + i * 256] = wsrc[tid + i * 256];
        __syncthreads();
        #pragma unroll 4
        for (int kk = 0; kk < 32; kk++) {
            float av[8], bv[6];
            #pragma unroll
            for (int i = 0; i < 8; i++) av[i] = s_q[(ty * 8 + i) * H + k0 + kk];
            #pragma unroll
            for (int j = 0; j < 6; j++) bv[j] = s_W[kk * H + tx + j * 64];
            #pragma unroll
            for (int i = 0; i < 8; i++)
                #pragma unroll
                for (int j = 0; j < 6; j++) acc[i][j] += av[i] * bv[j];
        }
        __syncthreads();
    }
    #pragma unroll
    for (int j = 0; j < 6; j++) {
        int h = tx + j * 64;
        float bb = b_b[h];
        float ps = 0.f;
        #pragma unroll
        for (int i = 0; i < 8; i++) ps += fmaxf(acc[i][j] + bb, 0.f);
        s_red[ty * H + h] = ps;
    }
    __syncthreads();
    if (ty == 0) {
        #pragma unroll
        for (int j = 0; j < 6; j++) {
            int h = tx + j * 64;
            float total = s_red[h] + s_red[H + h] + s_red[2 * H + h] + s_red[3 * H + h];
            float cs = 0.f;
            for (int a = 0; a < 32; a++) cs += s_cur[a * H + h];
            out[(size_t)m * H + h] = total + cs;
        }
    }
}

// ==========================================================================
extern "C" void kernel_launch(void* const* d_in, const int* in_sizes, int n_in,
                              void* d_out, int out_size)
{
    const float* f_atoms = (const float*)d_in[0];
    const float* f_bonds = (const float*)d_in[1];
    const float* W_i     = (const float*)d_in[2];
    const float* W_h     = (const float*)d_in[3];
    const float* W_o     = (const float*)d_in[4];
    const float* b_o     = (const float*)d_in[5];
    const float* W_a     = (const float*)d_in[6];
    const float* W_b     = (const float*)d_in[7];
    const float* b_b     = (const float*)d_in[8];
    const int*   a2b     = (const int*)d_in[9];
    const int*   b2a     = (const int*)d_in[10];
    const int*   b2revb  = (const int*)d_in[11];
    float*       out     = (float*)d_out;

    float *inp, *msgA, *msgB, *amsg, *atomh;
    cudaGetSymbolAddress((void**)&inp,   g_inp);
    cudaGetSymbolAddress((void**)&msgA,  g_msgA);
    cudaGetSymbolAddress((void**)&msgB,  g_msgB);
    cudaGetSymbolAddress((void**)&amsg,  g_amsg);
    cudaGetSymbolAddress((void**)&atomh, g_atomh);

    const dim3 blk(256);
    const dim3 gBond((NBD + 127) / 128, 3);
    const dim3 gAtom((NAT + 127) / 128, 3);
    const int  gGather = (NAT * (H / 4) + 255) / 256;

    // message^0 = relu(inp), inp = f_bonds @ W_i
    sgemm_k<0><<<gBond, blk>>>(NBD, BF, f_bonds, W_i, nullptr, nullptr,
                               inp, msgA, nullptr, nullptr, nullptr, nullptr, nullptr);

    // 3 message-passing steps (ping-pong A/B)
    float* cur = msgA;
    float* nxt = msgB;
    for (int d = 0; d < 3; d++) {
        gather_amsg_k<<<gGather, 256>>>(cur, a2b, amsg);
        sgemm_k<1><<<gBond, blk>>>(NBD, H, nullptr, W_h + (size_t)d * H * H, inp, nullptr,
                                   nullptr, nxt, amsg, cur, b2a, b2revb, nullptr);
        float* t = cur; cur = nxt; nxt = t;
    }

    // final a_msg + atom readout: atom_h = relu(concat(f_atoms, a_msg) @ W_o + b_o)
    gather_amsg_k<<<gGather, 256>>>(cur, a2b, amsg);
    sgemm_k<2><<<gAtom, blk>>>(NAT, KCAT, nullptr, W_o, nullptr, b_o,
                               nullptr, atomh, amsg, nullptr, nullptr, nullptr, f_atoms);

    // per-molecule attention + reduce
    cudaFuncSetAttribute(attention_k, cudaFuncAttributeMaxDynamicSharedMemorySize,
                         (int)ATT_SMEM);
    attention_k<<<MMOL, 256, ATT_SMEM>>>(atomh, W_a, W_b, b_b, out);
}